// round 17
// baseline (speedup 1.0000x reference)
#include <cuda_runtime.h>
#include <cstdint>

// out[t,:] = 1 / where(dmat[row(t),:]==0, BIG, dmat[row(t),:])
//   row(t) = venueid2coor[inputs_poi[t]]
// R15: single-block SMEM counting-sort prep (no lists, no grid barrier, no
// persistent state) + uniform row-sorted stream kernel (L2 dedups duplicate
// row reads; proven: 373MB @ 5.7TB/s, 65us).

#define N_POI    10000
#define V_SIZE   20000
#define N_TOK    6400

#define SEGMENTS 2
#define SEG_VEC  1250        // float4 per segment (2500 total per row)
#define FULL_IT  4           // 4*256 = 1024 vectors
#define TAIL     226         // 1250 - 1024

#define PT       1024        // prep threads
#define RPT      10          // rows per thread in scan (1000*10 = 10000)
#define TPT      7           // ceil(6400/1024) tokens per thread

__device__ int g_tok[N_TOK];   // tokens in row-sorted order
__device__ int g_row[N_TOK];   // row for each entry

__global__ void __launch_bounds__(PT) prep_kernel(
    const void* __restrict__ venueid2coor,
    const void* __restrict__ inputs_poi,
    int n_tok)
{
    __shared__ int s_count[N_POI];     // 40KB: counts -> offsets -> cursors
    __shared__ int s_scan[PT];         // 4KB
    __shared__ int s_poi64, s_v2c64;

    const int tid = threadIdx.x;

    for (int i = tid; i < N_POI; i += PT) s_count[i] = 0;

    if (tid == 0) {  // dtype detect: LE int64 small values -> odd words zero
        const unsigned int* poi = (const unsigned int*)inputs_poi;
        const unsigned int* v2c = (const unsigned int*)venueid2coor;
        int p = 1, v = 1;
        #pragma unroll
        for (int k = 1; k < 32; k += 2) {
            if (poi[k] != 0u) p = 0;
            if (v2c[k] != 0u) v = 0;
        }
        s_poi64 = p; s_v2c64 = v;
    }
    __syncthreads();
    const int poi64 = s_poi64, v2c64 = s_v2c64;

    // Pass 1: compute rows (kept in registers), histogram into smem.
    int myrow[TPT];
    int cnt = 0;
    for (int t = tid; t < n_tok; t += PT) {
        long long vid = poi64 ? ((const long long*)inputs_poi)[t]
                              : (long long)((const int*)inputs_poi)[t];
        if (vid < 0) vid = 0;
        if (vid >= V_SIZE) vid = V_SIZE - 1;

        long long row = v2c64 ? ((const long long*)venueid2coor)[vid]
                              : (long long)((const int*)venueid2coor)[vid];
        if (row < 0) row = 0;
        if (row >= N_POI) row = N_POI - 1;

        myrow[cnt++] = (int)row;
        atomicAdd(&s_count[(int)row], 1);
    }
    __syncthreads();

    // Exclusive prefix sum over s_count[0..N_POI): per-thread 10-row chunks,
    // then Hillis-Steele scan of the 1000 chunk sums.
    int local[RPT];
    int sum = 0;
    const int base = tid * RPT;
    if (base < N_POI) {
        #pragma unroll
        for (int k = 0; k < RPT; k++) {
            local[k] = sum;                 // exclusive within chunk
            sum += s_count[base + k];
        }
    }
    s_scan[tid] = (base < N_POI) ? sum : 0;
    __syncthreads();
    for (int off = 1; off < PT; off <<= 1) {
        int v = 0;
        if (tid >= off) v = s_scan[tid - off];
        __syncthreads();
        if (tid >= off) s_scan[tid] += v;
        __syncthreads();
    }
    if (base < N_POI) {
        int chunk_off = (tid == 0) ? 0 : s_scan[tid - 1];
        #pragma unroll
        for (int k = 0; k < RPT; k++)
            s_count[base + k] = chunk_off + local[k];   // start offsets
    }
    __syncthreads();

    // Pass 2: scatter tokens to row-sorted positions.
    for (int i = 0; i < cnt; i++) {
        int r = myrow[i];
        int pos = atomicAdd(&s_count[r], 1);
        g_tok[pos] = tid + i * PT;
        g_row[pos] = r;
    }
}

__device__ __forceinline__ float4 xform(float4 v)
{
    const float BIG = 9999999.99f;
    float4 r;
    r.x = __frcp_rn(v.x == 0.0f ? BIG : v.x);
    r.y = __frcp_rn(v.y == 0.0f ? BIG : v.y);
    r.z = __frcp_rn(v.z == 0.0f ? BIG : v.z);
    r.w = __frcp_rn(v.w == 0.0f ? BIG : v.w);
    return r;
}

// grid = (n_tok, SEGMENTS), block = 256. Every CTA does identical work.
__global__ void __launch_bounds__(256) stream_kernel(
    const float* __restrict__ dmat,
    float*       __restrict__ out,
    int n_tok)
{
    const int w = blockIdx.x;
    const int tid = threadIdx.x;

    const int row   = g_row[w];            // uniform -> broadcast
    const int token = g_tok[w];
    const int segbase = blockIdx.y * SEG_VEC;

    const float4* __restrict__ src =
        reinterpret_cast<const float4*>(dmat + (size_t)row * N_POI) + segbase;
    float4* __restrict__ dst =
        reinterpret_cast<float4*>(out + (size_t)token * N_POI) + segbase;

    // Caching loads: duplicate-row CTAs are adjacent in bid order -> L2 hits.
    // Streaming stores: output never re-read.
    float4 v[FULL_IT];
    #pragma unroll
    for (int k = 0; k < FULL_IT; k++)
        v[k] = __ldg(&src[tid + k * 256]);
    #pragma unroll
    for (int k = 0; k < FULL_IT; k++)
        __stcs(&dst[tid + k * 256], xform(v[k]));
    if (tid < TAIL) {
        float4 t4 = __ldg(&src[FULL_IT * 256 + tid]);
        __stcs(&dst[FULL_IT * 256 + tid], xform(t4));
    }
}

extern "C" void kernel_launch(void* const* d_in, const int* in_sizes, int n_in,
                              void* d_out, int out_size)
{
    const void*  venueid2coor = d_in[0];
    const void*  inputs_poi   = d_in[1];
    const float* dmat         = (const float*)d_in[2];
    float*       out          = (float*)d_out;

    int n_tok = in_sizes[1];
    if (n_tok > N_TOK) n_tok = N_TOK;

    prep_kernel<<<1, PT>>>(venueid2coor, inputs_poi, n_tok);

    dim3 grid(n_tok, SEGMENTS);
    stream_kernel<<<grid, 256>>>(dmat, out, n_tok);
}